// round 2
// baseline (speedup 1.0000x reference)
#include <cuda_runtime.h>
#include <math.h>

#define FEAT_I 512
#define H_DIM  1024
#define CODE   640
#define CODE_G 320
#define GROUPS 2
#define FEAT_G 256
#define B_SZ   8
#define T_SZ   4096
#define N_TOK  (B_SZ * T_SZ)   // 32768

#define BM 128
#define BN 128
#define BK 16

// Scratch (static device globals: allocation-free per harness rules)
__device__ float g_h[(size_t)N_TOK * H_DIM];       // 128 MB
__device__ float g_logits[(size_t)N_TOK * CODE];   // 80 MB
__device__ int   g_idx[N_TOK * GROUPS];

// ---------------------------------------------------------------------------
// GEMM1: h = relu(X @ W1 + b1);  X[m][k] = series[b, k, t], m = b*T + t
// A is effectively column-major (contiguous along m for fixed k).
// ---------------------------------------------------------------------------
__global__ void __launch_bounds__(256, 2) gemm1_kernel(
    const float* __restrict__ series, const float* __restrict__ W1,
    const float* __restrict__ b1)
{
    __shared__ float As[2][BK][BM + 4];
    __shared__ float Bs[2][BK][BN];

    const int m0  = blockIdx.y * BM;
    const int n0  = blockIdx.x * BN;
    const int tid = threadIdx.x;
    const int tx  = tid & 15, ty = tid >> 4;

    const int bb = m0 >> 12;          // batch index (BM=128 divides T)
    const int t0 = m0 & 4095;
    const float* Abase = series + (size_t)bb * (FEAT_I * T_SZ) + t0;

    const int kA = tid >> 5;          // 0..7 (second load handles kA+8)
    const int mA = (tid & 31) * 4;    // 0..124

    float acc[8][8];
#pragma unroll
    for (int i = 0; i < 8; i++)
#pragma unroll
        for (int j = 0; j < 8; j++) acc[i][j] = 0.f;

    // prologue: load tile 0
    {
        float4 v0 = *(const float4*)(Abase + (size_t)(kA)     * T_SZ + mA);
        float4 v1 = *(const float4*)(Abase + (size_t)(kA + 8) * T_SZ + mA);
        *(float4*)&As[0][kA][mA]     = v0;
        *(float4*)&As[0][kA + 8][mA] = v1;
        float4 w0 = *(const float4*)(W1 + (size_t)(kA)     * H_DIM + n0 + mA);
        float4 w1 = *(const float4*)(W1 + (size_t)(kA + 8) * H_DIM + n0 + mA);
        *(float4*)&Bs[0][kA][mA]     = w0;
        *(float4*)&Bs[0][kA + 8][mA] = w1;
    }
    __syncthreads();

    int buf = 0;
#pragma unroll 1
    for (int k0 = 0; k0 < FEAT_I; k0 += BK) {
        const bool more = (k0 + BK) < FEAT_I;
        float4 va0, va1, vb0, vb1;
        if (more) {
            const int kn = k0 + BK;
            va0 = *(const float4*)(Abase + (size_t)(kn + kA)     * T_SZ + mA);
            va1 = *(const float4*)(Abase + (size_t)(kn + kA + 8) * T_SZ + mA);
            vb0 = *(const float4*)(W1 + (size_t)(kn + kA)     * H_DIM + n0 + mA);
            vb1 = *(const float4*)(W1 + (size_t)(kn + kA + 8) * H_DIM + n0 + mA);
        }
#pragma unroll
        for (int kb = 0; kb < BK; kb++) {
            float4 a0 = *(const float4*)&As[buf][kb][ty * 4];
            float4 a1 = *(const float4*)&As[buf][kb][ty * 4 + 64];
            float4 c0 = *(const float4*)&Bs[buf][kb][tx * 4];
            float4 c1 = *(const float4*)&Bs[buf][kb][tx * 4 + 64];
            float a[8] = {a0.x, a0.y, a0.z, a0.w, a1.x, a1.y, a1.z, a1.w};
            float bv[8] = {c0.x, c0.y, c0.z, c0.w, c1.x, c1.y, c1.z, c1.w};
#pragma unroll
            for (int i = 0; i < 8; i++)
#pragma unroll
                for (int j = 0; j < 8; j++)
                    acc[i][j] = fmaf(a[i], bv[j], acc[i][j]);
        }
        if (more) {
            *(float4*)&As[buf ^ 1][kA][mA]     = va0;
            *(float4*)&As[buf ^ 1][kA + 8][mA] = va1;
            *(float4*)&Bs[buf ^ 1][kA][mA]     = vb0;
            *(float4*)&Bs[buf ^ 1][kA + 8][mA] = vb1;
            __syncthreads();
            buf ^= 1;
        }
    }

#pragma unroll
    for (int i = 0; i < 8; i++) {
        const int m = m0 + ty * 4 + (i & 3) + ((i >> 2) * 64);
#pragma unroll
        for (int jj = 0; jj < 2; jj++) {
            const int n = n0 + tx * 4 + jj * 64;
            float4 o;
            o.x = fmaxf(acc[i][jj * 4 + 0] + b1[n + 0], 0.f);
            o.y = fmaxf(acc[i][jj * 4 + 1] + b1[n + 1], 0.f);
            o.z = fmaxf(acc[i][jj * 4 + 2] + b1[n + 2], 0.f);
            o.w = fmaxf(acc[i][jj * 4 + 3] + b1[n + 3], 0.f);
            *(float4*)&g_h[(size_t)m * H_DIM + n] = o;
        }
    }
}

// ---------------------------------------------------------------------------
// GEMM2: logits = H @ W2 + b2;  H row-major (transpose-on-shared-store)
// ---------------------------------------------------------------------------
__global__ void __launch_bounds__(256, 2) gemm2_kernel(
    const float* __restrict__ W2, const float* __restrict__ b2)
{
    __shared__ float As[2][BK][BM + 4];
    __shared__ float Bs[2][BK][BN];

    const int m0  = blockIdx.y * BM;
    const int n0  = blockIdx.x * BN;
    const int tid = threadIdx.x;
    const int tx  = tid & 15, ty = tid >> 4;

    // A-load slots: per thread (m, k4) pairs; m = tid>>2 (+64), k4 = (tid&3)*4
    const int mT = tid >> 2;
    const int k4 = (tid & 3) * 4;
    // B-load slots
    const int kB = tid >> 5;
    const int nB = (tid & 31) * 4;

    float acc[8][8];
#pragma unroll
    for (int i = 0; i < 8; i++)
#pragma unroll
        for (int j = 0; j < 8; j++) acc[i][j] = 0.f;

    // prologue
    {
#pragma unroll
        for (int h = 0; h < 2; h++) {
            const int m = mT + h * 64;
            float4 v = *(const float4*)(g_h + (size_t)(m0 + m) * H_DIM + k4);
            As[0][k4 + 0][m] = v.x;
            As[0][k4 + 1][m] = v.y;
            As[0][k4 + 2][m] = v.z;
            As[0][k4 + 3][m] = v.w;
        }
        float4 w0 = *(const float4*)(W2 + (size_t)(kB)     * CODE + n0 + nB);
        float4 w1 = *(const float4*)(W2 + (size_t)(kB + 8) * CODE + n0 + nB);
        *(float4*)&Bs[0][kB][nB]     = w0;
        *(float4*)&Bs[0][kB + 8][nB] = w1;
    }
    __syncthreads();

    int buf = 0;
#pragma unroll 1
    for (int k0 = 0; k0 < H_DIM; k0 += BK) {
        const bool more = (k0 + BK) < H_DIM;
        float4 va0, va1, vb0, vb1;
        if (more) {
            const int kn = k0 + BK;
            va0 = *(const float4*)(g_h + (size_t)(m0 + mT)      * H_DIM + kn + k4);
            va1 = *(const float4*)(g_h + (size_t)(m0 + mT + 64) * H_DIM + kn + k4);
            vb0 = *(const float4*)(W2 + (size_t)(kn + kB)     * CODE + n0 + nB);
            vb1 = *(const float4*)(W2 + (size_t)(kn + kB + 8) * CODE + n0 + nB);
        }
#pragma unroll
        for (int kb = 0; kb < BK; kb++) {
            float4 a0 = *(const float4*)&As[buf][kb][ty * 4];
            float4 a1 = *(const float4*)&As[buf][kb][ty * 4 + 64];
            float4 c0 = *(const float4*)&Bs[buf][kb][tx * 4];
            float4 c1 = *(const float4*)&Bs[buf][kb][tx * 4 + 64];
            float a[8] = {a0.x, a0.y, a0.z, a0.w, a1.x, a1.y, a1.z, a1.w};
            float bv[8] = {c0.x, c0.y, c0.z, c0.w, c1.x, c1.y, c1.z, c1.w};
#pragma unroll
            for (int i = 0; i < 8; i++)
#pragma unroll
                for (int j = 0; j < 8; j++)
                    acc[i][j] = fmaf(a[i], bv[j], acc[i][j]);
        }
        if (more) {
            As[buf ^ 1][k4 + 0][mT]      = va0.x;
            As[buf ^ 1][k4 + 1][mT]      = va0.y;
            As[buf ^ 1][k4 + 2][mT]      = va0.z;
            As[buf ^ 1][k4 + 3][mT]      = va0.w;
            As[buf ^ 1][k4 + 0][mT + 64] = va1.x;
            As[buf ^ 1][k4 + 1][mT + 64] = va1.y;
            As[buf ^ 1][k4 + 2][mT + 64] = va1.z;
            As[buf ^ 1][k4 + 3][mT + 64] = va1.w;
            *(float4*)&Bs[buf ^ 1][kB][nB]     = vb0;
            *(float4*)&Bs[buf ^ 1][kB + 8][nB] = vb1;
            __syncthreads();
            buf ^= 1;
        }
    }

#pragma unroll
    for (int i = 0; i < 8; i++) {
        const int m = m0 + ty * 4 + (i & 3) + ((i >> 2) * 64);
#pragma unroll
        for (int jj = 0; jj < 2; jj++) {
            const int n = n0 + tx * 4 + jj * 64;
            float4 o;
            o.x = acc[i][jj * 4 + 0] + b2[n + 0];
            o.y = acc[i][jj * 4 + 1] + b2[n + 1];
            o.z = acc[i][jj * 4 + 2] + b2[n + 2];
            o.w = acc[i][jj * 4 + 3] + b2[n + 3];
            *(float4*)&g_logits[(size_t)m * CODE + n] = o;
        }
    }
}

// ---------------------------------------------------------------------------
// Gumbel + argmax per (token, group). One warp per slot.
// argmax(softmax((logits+g)/TAU)) == argmax(logits+g); first-occurrence ties.
// ---------------------------------------------------------------------------
__global__ void __launch_bounds__(256) argmax_kernel(
    const float* __restrict__ gumbel_u, float* __restrict__ idx_out_f)
{
    const int warp = (blockIdx.x * blockDim.x + threadIdx.x) >> 5;
    const int lane = threadIdx.x & 31;
    if (warp >= N_TOK * GROUPS) return;
    const int n = warp >> 1, g = warp & 1;
    const float* lrow = g_logits + (size_t)n * CODE + g * CODE_G;
    const float* urow = gumbel_u + (size_t)n * CODE + g * CODE_G;

    float best = -INFINITY;
    int bi = 0x7fffffff;
#pragma unroll
    for (int c = lane; c < CODE_G; c += 32) {
        float u  = urow[c];
        float gn = -logf(-logf(u + 1e-10f) + 1e-10f);
        float v  = lrow[c] + gn;
        if (v > best) { best = v; bi = c; }   // strided: lane-local keeps earliest
    }
#pragma unroll
    for (int off = 16; off > 0; off >>= 1) {
        float ov = __shfl_down_sync(0xffffffffu, best, off);
        int   oi = __shfl_down_sync(0xffffffffu, bi, off);
        if (ov > best || (ov == best && oi < bi)) { best = ov; bi = oi; }
    }
    if (lane == 0) {
        g_idx[warp] = bi;
        idx_out_f[warp] = (float)bi;   // maxidx_series, (B,T,2) row-major == slot order
    }
}

// ---------------------------------------------------------------------------
// Gather: q_series[b, f, t] = codebook[f/256, idx[b,t,f/256], f%256]
// Coalesced writes along t; codebook (640 KB) stays L2-resident.
// ---------------------------------------------------------------------------
__global__ void __launch_bounds__(256) gather_kernel(
    const float* __restrict__ codebook, float* __restrict__ out)
{
    const unsigned e = blockIdx.x * 256u + threadIdx.x;  // < 2^24
    const int t  = e & 4095;
    const int f  = (e >> 12) & 511;
    const int b  = e >> 21;
    const int g  = f >> 8;
    const int fs = f & 255;
    const int token = (b << 12) | t;
    const int idx = g_idx[token * 2 + g];
    out[e] = codebook[((g * CODE_G + idx) << 8) + fs];
}

// ---------------------------------------------------------------------------
extern "C" void kernel_launch(void* const* d_in, const int* in_sizes, int n_in,
                              void* d_out, int out_size)
{
    const float* series   = (const float*)d_in[0];
    const float* gumbel_u = (const float*)d_in[1];
    const float* W1       = (const float*)d_in[2];
    const float* b1       = (const float*)d_in[3];
    const float* W2       = (const float*)d_in[4];
    const float* b2       = (const float*)d_in[5];
    const float* codebook = (const float*)d_in[6];
    float* out = (float*)d_out;
    // Layout: q_series (B*512*T floats) first, then maxidx (N*2) cast to float.
    float* idx_out = out + ((size_t)out_size - (size_t)N_TOK * GROUPS);

    gemm1_kernel<<<dim3(H_DIM / BN, N_TOK / BM), 256>>>(series, W1, b1);
    gemm2_kernel<<<dim3(CODE / BN, N_TOK / BM), 256>>>(W2, b2);
    argmax_kernel<<<(N_TOK * GROUPS * 32) / 256, 256>>>(gumbel_u, idx_out);
    gather_kernel<<<(N_TOK * FEAT_I) / 256, 256>>>(codebook, out);
}

// round 7
// speedup vs baseline: 1.5873x; 1.5873x over previous
#include <cuda_runtime.h>
#include <cuda_bf16.h>
#include <math.h>
#include <stdint.h>

#define FEAT_I 512
#define H_DIM  1024
#define CODE   640
#define CODE_G 320
#define B_SZ   8
#define T_SZ   4096
#define N_TOK  32768

#define DELTA   0.008f
#define FIXMAX  16384

// ---------------- scratch (static device globals; no allocation) -----------
__device__ __nv_bfloat16 g_xb[(size_t)N_TOK * FEAT_I];
__device__ __nv_bfloat16 g_w1b[(size_t)H_DIM * FEAT_I];
__device__ __nv_bfloat16 g_w2b[(size_t)CODE * H_DIM];
__device__ __nv_bfloat16 g_hb[(size_t)N_TOK * H_DIM];
__device__ __nv_bfloat16 g_lb[(size_t)N_TOK * CODE];
__device__ int g_idx[N_TOK * 2];
__device__ int g_fixcnt;
__device__ int g_fixlist[FIXMAX];

// ---------------- helpers ---------------------------------------------------
__device__ __forceinline__ uint32_t smem_u32(const void* p) {
    uint32_t a;
    asm("{ .reg .u64 t; cvta.to.shared.u64 t, %1; cvt.u32.u64 %0, t; }"
        : "=r"(a) : "l"(p));
    return a;
}

__device__ __forceinline__ uint32_t lds32(uint32_t a) {
    uint32_t v;
    asm volatile("ld.shared.b32 %0, [%1];" : "=r"(v) : "r"(a));
    return v;
}

__device__ __forceinline__ void mma16816(float* d, const uint32_t* a,
                                         uint32_t b0, uint32_t b1) {
    asm volatile(
        "mma.sync.aligned.m16n8k16.row.col.f32.bf16.bf16.f32 "
        "{%0,%1,%2,%3}, {%4,%5,%6,%7}, {%8,%9}, {%0,%1,%2,%3};"
        : "+f"(d[0]), "+f"(d[1]), "+f"(d[2]), "+f"(d[3])
        : "r"(a[0]), "r"(a[1]), "r"(a[2]), "r"(a[3]), "r"(b0), "r"(b1));
}

// ---------------- transpose fp32 -> bf16: OUT[c][r] = IN[r][c] --------------
__global__ void transpose_bf16_kernel(const float* __restrict__ in,
                                      __nv_bfloat16* __restrict__ out,
                                      int R, int C, size_t ibs, size_t obs)
{
    __shared__ float tile[32][33];
    in += (size_t)blockIdx.z * ibs;
    const size_t ob = (size_t)blockIdx.z * obs;
    const int c0 = blockIdx.x * 32, r0 = blockIdx.y * 32;
    const int tx = threadIdx.x, ty = threadIdx.y;
#pragma unroll
    for (int j = 0; j < 4; j++)
        tile[ty + 8 * j][tx] = in[(size_t)(r0 + ty + 8 * j) * C + c0 + tx];
    __syncthreads();
#pragma unroll
    for (int j = 0; j < 4; j++)
        out[ob + (size_t)(c0 + ty + 8 * j) * R + r0 + tx] =
            __float2bfloat16(tile[tx][ty + 8 * j]);
}

__global__ void reset_kernel() { g_fixcnt = 0; }

// ---------------- bf16 HMMA GEMM -------------------------------------------
// O[m][n] = act(sum_k A[m][k]*B[n][k] + bias[n]);  A=[M][K], B=[N][K], bf16.
#define BM 128
#define BN 128
#define BK 32
#define ROWB 80                 // padded smem row: 64B data + 16B pad
#define STG_A (128 * ROWB)      // 10240
#define STG   (2 * STG_A)       // 20480
#define PIPE_SMEM (3 * STG)     // 61440

template<int K, bool RELU>
__global__ void __launch_bounds__(256)
gemm_bf16_kernel(const __nv_bfloat16* __restrict__ A,
                 const __nv_bfloat16* __restrict__ Bw,
                 const float* __restrict__ bias,
                 __nv_bfloat16* __restrict__ O, int ldO)
{
    extern __shared__ char smem[];
    const uint32_t sb = smem_u32(smem);
    const int tid = threadIdx.x, lane = tid & 31, wid = tid >> 5;
    const int m0 = blockIdx.y * BM, n0 = blockIdx.x * BN;
    const int mbase = (wid & 3) * 32, nbase = (wid >> 2) * 64;

    // cp.async mapping: row = tid>>1; two 16B chunks at byte (tid&1)*32, +16
    const int ldr = tid >> 1;
    const uint64_t gA = (uint64_t)__cvta_generic_to_global(A) +
                        ((size_t)(m0 + ldr) * K + (size_t)(tid & 1) * 16) * 2;
    const uint64_t gB = (uint64_t)__cvta_generic_to_global(Bw) +
                        ((size_t)(n0 + ldr) * K + (size_t)(tid & 1) * 16) * 2;
    const uint32_t sA = sb + ldr * ROWB + (tid & 1) * 32;
    const uint32_t sB = sA + STG_A;

    auto issue = [&](int c) {
        const uint32_t o = (uint32_t)(c % 3) * STG;
        const uint64_t ga = gA + (size_t)c * BK * 2;
        const uint64_t gb = gB + (size_t)c * BK * 2;
        asm volatile(
            "cp.async.cg.shared.global [%0], [%1], 16;\n\t"
            "cp.async.cg.shared.global [%2], [%3], 16;\n\t"
            "cp.async.cg.shared.global [%4], [%5], 16;\n\t"
            "cp.async.cg.shared.global [%6], [%7], 16;\n\t"
            :: "r"(sA + o), "l"(ga), "r"(sA + o + 16), "l"(ga + 16),
               "r"(sB + o), "l"(gb), "r"(sB + o + 16), "l"(gb + 16)
            : "memory");
        asm volatile("cp.async.commit_group;" ::: "memory");
    };

    float acc[2][8][4];
#pragma unroll
    for (int i = 0; i < 2; i++)
#pragma unroll
        for (int j = 0; j < 8; j++)
#pragma unroll
            for (int r = 0; r < 4; r++) acc[i][j][r] = 0.f;

    issue(0); issue(1);

    const int NC = K / BK;
    const int qr = lane >> 2;            // 0..7
    const int qc = (lane & 3) * 4;       // byte offset within k16

#pragma unroll 1
    for (int c = 0; c < NC; c++) {
        asm volatile("cp.async.wait_group 1;" ::: "memory");
        __syncthreads();
        if (c + 2 < NC) issue(c + 2);
        else asm volatile("cp.async.commit_group;" ::: "memory");

        const uint32_t bb = sb + (uint32_t)(c % 3) * STG;
#pragma unroll
        for (int kk = 0; kk < 2; kk++) {
            const uint32_t kb = bb + kk * 32 + qc;
            uint32_t af[2][4];
#pragma unroll
            for (int i = 0; i < 2; i++) {
                const uint32_t r0 = kb + (mbase + 16 * i + qr) * ROWB;
                af[i][0] = lds32(r0);
                af[i][1] = lds32(r0 + 8 * ROWB);
                af[i][2] = lds32(r0 + 16);
                af[i][3] = lds32(r0 + 8 * ROWB + 16);
            }
#pragma unroll
            for (int j = 0; j < 8; j++) {
                const uint32_t rb = kb + STG_A + (nbase + 8 * j + qr) * ROWB;
                const uint32_t b0 = lds32(rb), b1v = lds32(rb + 16);
                mma16816(acc[0][j], af[0], b0, b1v);
                mma16816(acc[1][j], af[1], b0, b1v);
            }
        }
    }

    // epilogue: bias (+relu), stage bf16 in smem, 16B-coalesced stores
    __syncthreads();
    __nv_bfloat16* st = (__nv_bfloat16*)smem;
#pragma unroll
    for (int j = 0; j < 8; j++) {
        const int nb = nbase + 8 * j + (lane & 3) * 2;
        const float2 bs = *(const float2*)(bias + n0 + nb);
#pragma unroll
        for (int i = 0; i < 2; i++) {
            float v0 = acc[i][j][0] + bs.x, v1 = acc[i][j][1] + bs.y;
            float v2 = acc[i][j][2] + bs.x, v3 = acc[i][j][3] + bs.y;
            if (RELU) {
                v0 = fmaxf(v0, 0.f); v1 = fmaxf(v1, 0.f);
                v2 = fmaxf(v2, 0.f); v3 = fmaxf(v3, 0.f);
            }
            const int mr = mbase + 16 * i + qr;
            *(__nv_bfloat162*)(st + mr * 136 + nb) = __floats2bfloat162_rn(v0, v1);
            *(__nv_bfloat162*)(st + (mr + 8) * 136 + nb) = __floats2bfloat162_rn(v2, v3);
        }
    }
    __syncthreads();
#pragma unroll
    for (int v = 0; v < 8; v++) {
        const int idx = tid + v * 256;
        const int row = idx >> 4, c8 = (idx & 15) * 8;
        *(uint4*)(O + (size_t)(m0 + row) * ldO + n0 + c8) =
            *(const uint4*)(st + row * 136 + c8);
    }
}

// ---------------- gumbel + argmax with top-2 margin flag --------------------
__global__ void __launch_bounds__(256) argmax_kernel(
    const float* __restrict__ gumbel_u, float* __restrict__ idx_out_f)
{
    const int warp = (blockIdx.x * blockDim.x + threadIdx.x) >> 5;
    const int lane = threadIdx.x & 31;
    if (warp >= N_TOK * 2) return;
    const int n = warp >> 1, g = warp & 1;
    const __nv_bfloat16* lrow = g_lb + (size_t)n * CODE + g * CODE_G;
    const float* urow = gumbel_u + (size_t)n * CODE + g * CODE_G;

    float b1v = -INFINITY, b2v = -INFINITY;
    int bi = 0x7fffffff;
#pragma unroll
    for (int c = lane; c < CODE_G; c += 32) {
        float u  = urow[c];
        float gn = -logf(-logf(u + 1e-10f) + 1e-10f);
        float v  = __bfloat162float(lrow[c]) + gn;
        if (v > b1v) { b2v = b1v; b1v = v; bi = c; }
        else if (v > b2v) b2v = v;
    }
#pragma unroll
    for (int off = 16; off > 0; off >>= 1) {
        float o1 = __shfl_down_sync(0xffffffffu, b1v, off);
        float o2 = __shfl_down_sync(0xffffffffu, b2v, off);
        int   oi = __shfl_down_sync(0xffffffffu, bi, off);
        if (o1 > b1v || (o1 == b1v && oi < bi)) {
            b2v = fmaxf(b1v, o2); b1v = o1; bi = oi;
        } else {
            b2v = fmaxf(b2v, o1);
        }
    }
    if (lane == 0) {
        g_idx[warp] = bi;
        idx_out_f[warp] = (float)bi;
        if (b1v - b2v < DELTA) {
            int p = atomicAdd(&g_fixcnt, 1);
            if (p < FIXMAX) g_fixlist[p] = warp;
        }
    }
}

// ---------------- exact fp32 fixup for ambiguous slots ----------------------
__global__ void __launch_bounds__(256) fixup_kernel(
    const float* __restrict__ series, const float* __restrict__ W1,
    const float* __restrict__ b1, const float* __restrict__ W2,
    const float* __restrict__ b2, const float* __restrict__ gumbel_u,
    float* __restrict__ idx_out_f)
{
    __shared__ float xs[FEAT_I];
    __shared__ float hs[H_DIM];
    __shared__ float rv[256];
    __shared__ int   ri[256];
    const int tid = threadIdx.x;
    const int cnt = min(g_fixcnt, FIXMAX);

    for (int e = blockIdx.x; e < cnt; e += gridDim.x) {
        const int slot = g_fixlist[e];
        const int n = slot >> 1, g = slot & 1;
        const int b = n >> 12, t = n & 4095;
        const int gbase = g * CODE_G;

        // exact x row from series (column read)
        for (int k = tid; k < FEAT_I; k += 256)
            xs[k] = series[((size_t)b * FEAT_I + k) * T_SZ + t];
        __syncthreads();

        // exact h row
        for (int j = tid; j < H_DIM; j += 256) {
            float a = b1[j];
            for (int k = 0; k < FEAT_I; k++)
                a = fmaf(xs[k], W1[(size_t)k * H_DIM + j], a);
            hs[j] = fmaxf(a, 0.f);
        }
        __syncthreads();

        // exact logits + gumbel for this group's 320 codes
        float v0 = -INFINITY, v1 = -INFINITY;
        {
            float a = b2[gbase + tid];
            for (int k = 0; k < H_DIM; k++)
                a = fmaf(hs[k], W2[(size_t)k * CODE + gbase + tid], a);
            float u = gumbel_u[(size_t)n * CODE + gbase + tid];
            v0 = a + (-logf(-logf(u + 1e-10f) + 1e-10f));
        }
        if (tid < CODE_G - 256) {
            const int c = tid + 256;
            float a = b2[gbase + c];
            for (int k = 0; k < H_DIM; k++)
                a = fmaf(hs[k], W2[(size_t)k * CODE + gbase + c], a);
            float u = gumbel_u[(size_t)n * CODE + gbase + c];
            v1 = a + (-logf(-logf(u + 1e-10f) + 1e-10f));
        }
        float bv = v0; int bi = tid;
        if (v1 > bv) { bv = v1; bi = tid + 256; }
        rv[tid] = bv; ri[tid] = bi;
        __syncthreads();
        for (int s = 128; s > 0; s >>= 1) {
            if (tid < s) {
                if (rv[tid + s] > rv[tid] ||
                    (rv[tid + s] == rv[tid] && ri[tid + s] < ri[tid])) {
                    rv[tid] = rv[tid + s]; ri[tid] = ri[tid + s];
                }
            }
            __syncthreads();
        }
        if (tid == 0) {
            g_idx[slot] = ri[0];
            idx_out_f[slot] = (float)ri[0];
        }
        __syncthreads();
    }
}

// ---------------- gather: tiled, coalesced reads AND writes -----------------
__global__ void __launch_bounds__(256) gather_kernel(
    const float* __restrict__ codebook, float* __restrict__ out)
{
    __shared__ float cb[32 * 257];
    __shared__ int   sidx[32];
    const int t0 = (blockIdx.x & 127) * 32;
    const int g  = (blockIdx.x >> 7) & 1;
    const int b  = blockIdx.x >> 8;
    const int tid = threadIdx.x;

    if (tid < 32)
        sidx[tid] = g_idx[((b << 12) + t0 + tid) * 2 + g];
    __syncthreads();

#pragma unroll
    for (int it = 0; it < 8; it++) {
        const int j = tid + it * 256;
        const int row = j >> 6, c4 = (j & 63) * 4;
        float4 v = *(const float4*)(codebook + (((size_t)g * CODE_G + sidx[row]) << 8) + c4);
        float* p = cb + row * 257 + c4;
        p[0] = v.x; p[1] = v.y; p[2] = v.z; p[3] = v.w;
    }
    __syncthreads();

#pragma unroll
    for (int it = 0; it < 8; it++) {
        const int j = tid + it * 256;
        const int f = j >> 3, t4 = (j & 7) * 4;
        float4 v;
        v.x = cb[(t4 + 0) * 257 + f];
        v.y = cb[(t4 + 1) * 257 + f];
        v.z = cb[(t4 + 2) * 257 + f];
        v.w = cb[(t4 + 3) * 257 + f];
        *(float4*)(out + ((size_t)(b * 512 + g * 256 + f) << 12) + t0 + t4) = v;
    }
}

// ---------------------------------------------------------------------------
extern "C" void kernel_launch(void* const* d_in, const int* in_sizes, int n_in,
                              void* d_out, int out_size)
{
    const float* series   = (const float*)d_in[0];
    const float* gumbel_u = (const float*)d_in[1];
    const float* W1       = (const float*)d_in[2];
    const float* b1       = (const float*)d_in[3];
    const float* W2       = (const float*)d_in[4];
    const float* b2       = (const float*)d_in[5];
    const float* codebook = (const float*)d_in[6];
    float* out = (float*)d_out;
    float* idx_out = out + ((size_t)out_size - (size_t)N_TOK * 2);

    __nv_bfloat16 *xb, *w1b, *w2b, *hb, *lb;
    cudaGetSymbolAddress((void**)&xb,  g_xb);
    cudaGetSymbolAddress((void**)&w1b, g_w1b);
    cudaGetSymbolAddress((void**)&w2b, g_w2b);
    cudaGetSymbolAddress((void**)&hb,  g_hb);
    cudaGetSymbolAddress((void**)&lb,  g_lb);

    cudaFuncSetAttribute(gemm_bf16_kernel<FEAT_I, true>,
                         cudaFuncAttributeMaxDynamicSharedMemorySize, PIPE_SMEM);
    cudaFuncSetAttribute(gemm_bf16_kernel<H_DIM, false>,
                         cudaFuncAttributeMaxDynamicSharedMemorySize, PIPE_SMEM);

    // pack/transpose inputs to bf16
    transpose_bf16_kernel<<<dim3(T_SZ / 32, FEAT_I / 32, B_SZ), dim3(32, 8)>>>(
        series, xb, FEAT_I, T_SZ, (size_t)FEAT_I * T_SZ, (size_t)T_SZ * FEAT_I);
    transpose_bf16_kernel<<<dim3(H_DIM / 32, FEAT_I / 32, 1), dim3(32, 8)>>>(
        W1, w1b, FEAT_I, H_DIM, 0, 0);
    transpose_bf16_kernel<<<dim3(CODE / 32, H_DIM / 32, 1), dim3(32, 8)>>>(
        W2, w2b, H_DIM, CODE, 0, 0);
    reset_kernel<<<1, 1>>>();

    // GEMM1: h = relu(X W1 + b1)  (bf16 out)
    gemm_bf16_kernel<FEAT_I, true><<<dim3(H_DIM / BN, N_TOK / BM), 256, PIPE_SMEM>>>(
        xb, w1b, b1, hb, H_DIM);
    // GEMM2: logits = h W2 + b2   (bf16 out)
    gemm_bf16_kernel<H_DIM, false><<<dim3(CODE / BN, N_TOK / BM), 256, PIPE_SMEM>>>(
        hb, w2b, b2, lb, CODE);

    argmax_kernel<<<(N_TOK * 2 * 32) / 256, 256>>>(gumbel_u, idx_out);
    fixup_kernel<<<256, 256>>>(series, W1, b1, W2, b2, gumbel_u, idx_out);
    gather_kernel<<<B_SZ * 2 * (T_SZ / 32), 256>>>(codebook, out);
}